// round 17
// baseline (speedup 1.0000x reference)
#include <cuda_runtime.h>
#include <cuda_fp16.h>
#include <cstdint>

#define T_LEN 8192
#define CCH   512
#define BATCH 8
#define NELEM (BATCH * CCH * T_LEN)

__device__ __half g_bufM[NELEM];            // conv1 output (f16, [B][C][T])
__device__ __half g_bufT[NELEM];            // act output, transposed (f16, [B][T][C])

#define WPERM_U4 (4 * 16 * 6 * 8 * 32)     // 98304 uint4 = 1.5 MB
__device__ uint4 g_wperm1[WPERM_U4];
__device__ uint4 g_wperm2[WPERM_U4];

// ---------------------------------------------------------------------------
__device__ __forceinline__ uint32_t smem_u32(const void* p) {
    uint32_t a;
    asm("{ .reg .u64 t; cvta.to.shared.u64 t, %1; cvt.u32.u64 %0, t; }"
        : "=r"(a) : "l"(p));
    return a;
}
__device__ __forceinline__ uint32_t pack_f16x2(float lo, float hi) {
    uint32_t r;
    asm("cvt.rn.f16x2.f32 %0, %1, %2;" : "=r"(r) : "f"(hi), "f"(lo));
    return r;
}
__device__ __forceinline__ void cp_async16(uint32_t dst, const void* src) {
    asm volatile("cp.async.cg.shared.global [%0], [%1], 16;"
                 :: "r"(dst), "l"(src));
}
__device__ __forceinline__ void cp_async16s(uint32_t dst, const void* src, uint32_t sz) {
    asm volatile("cp.async.cg.shared.global [%0], [%1], 16, %2;"
                 :: "r"(dst), "l"(src), "r"(sz));
}
__device__ __forceinline__ void cp_commit() {
    asm volatile("cp.async.commit_group;" ::: "memory");
}
template <int N>
__device__ __forceinline__ void cp_wait() {
    asm volatile("cp.async.wait_group %0;" :: "n"(N) : "memory");
}
__device__ __forceinline__ void mma_f16(float* d, const uint32_t* a, const uint32_t* b) {
    asm volatile(
        "mma.sync.aligned.m16n8k16.row.col.f32.f16.f16.f32 "
        "{%0,%1,%2,%3}, {%4,%5,%6,%7}, {%8,%9}, {%0,%1,%2,%3};"
        : "+f"(d[0]), "+f"(d[1]), "+f"(d[2]), "+f"(d[3])
        : "r"(a[0]), "r"(a[1]), "r"(a[2]), "r"(a[3]), "r"(b[0]), "r"(b[1]));
}
__device__ __forceinline__ void ldsm_x4(uint32_t& r0, uint32_t& r1,
                                        uint32_t& r2, uint32_t& r3, uint32_t addr) {
    asm volatile("ldmatrix.sync.aligned.m8n8.x4.shared.b16 {%0,%1,%2,%3}, [%4];"
                 : "=r"(r0), "=r"(r1), "=r"(r2), "=r"(r3) : "r"(addr));
}

// ---------------------------------------------------------------------------
// Weight permutation: K-dim = ci (3 separate kk GEMMs).
// ---------------------------------------------------------------------------
__global__ __launch_bounds__(256) void permute_w(
    const float* __restrict__ w, uint4* __restrict__ wp)
{
    const int u = blockIdx.x * 256 + threadIdx.x;
    const int lane = u & 31;
    const int rest = u >> 5;
    const int mt = rest & 7;
    const int g  = (rest >> 3) % 6;
    const int sc = (rest >> 3) / 6;
    const int ks = g & 1;
    const int kk = g >> 1;
    const int st = sc & 15;
    const int cb = sc >> 4;

    uint4 v;
    uint32_t* o = &v.x;
#pragma unroll
    for (int rg = 0; rg < 4; ++rg) {
        const int m8 = (lane >> 2) + 8 * (rg & 1);
        const int ci = st * 32 + ks * 16 + 2 * (lane & 3) + 8 * (rg >> 1);
        const int co = cb * 128 + mt * 16 + m8;
        const float w0 = w[(size_t)co * 1536 + ci * 3 + kk];
        const float w1 = w[(size_t)co * 1536 + (ci + 1) * 3 + kk];
        o[rg] = pack_f16x2(w0, w1);
    }
    wp[u] = v;
}

// ---------------------------------------------------------------------------
// Fused Act + Transpose v2: in [B][C][T] (Tin) -> out f16 [B][T][C].
// Block 64c x 64t. Phase 1: 140 sv values per channel computed ONCE into smem
// (2.19 sin/output). Phase 2: sliding downsample from smem sv, zt staging
// (reuses sx region), coalesced [t][C] writes.
// ---------------------------------------------------------------------------
#define SXW 81
#define SVP 141
#define ACT_SXZ_W  (64 * SXW)               // 5184 (>= zt 4096)
#define ACT_SMEM   ((ACT_SXZ_W + 64 * SVP) * 4)   // 56832 B

template <typename Tin>
__global__ __launch_bounds__(256) void actT_kernel(
    const Tin* __restrict__ in, __half* __restrict__ outT,
    const float* __restrict__ la, const float* __restrict__ lb,
    const float* __restrict__ fup, const float* __restrict__ fdn)
{
    extern __shared__ float dsm[];
    float* sx = dsm;                  // [64][81], reused as zt [64][64] in phase 2
    float* sv = dsm + ACT_SXZ_W;      // [64][141]
    __shared__ float su[12], sd[12];

    const int t0 = blockIdx.x * 64;
    const int c0 = blockIdx.y * 64;
    const int b  = blockIdx.z;
    const int tid = threadIdx.x;

    if (tid < 12) { su[tid] = fup[tid]; sd[tid] = fdn[tid]; }

    // load x window: rows c0..c0+63, cols t0-8..t0+72 (clamped)
    for (int i = tid; i < 64 * SXW; i += 256) {
        const int r = i / SXW;
        const int j = i - r * SXW;
        int g = t0 - 8 + j;
        g = min(max(g, 0), T_LEN - 1);
        sx[i] = (float)in[((size_t)(b * CCH + c0 + r)) * T_LEN + g];
    }
    __syncthreads();

    // ---- phase 1: sv[ch][j] = v(2*t0 - 5 + j), j = 0..139 ----
    {
        const int ch  = tid & 63;
        const int grp = tid >> 6;         // 0..3, 35 j's each
        const int c   = c0 + ch;
        const float alpha = __expf(la[c]);
        const float invb  = 1.0f / (__expf(lb[c]) + 1e-9f);
        const float u0=su[0],u1=su[1],u2=su[2],u3=su[3],u4=su[4],u5=su[5],
                    u6=su[6],u7=su[7],u8=su[8],u9=su[9],u10=su[10],u11=su[11];
        const float* xrow = &sx[ch * SXW];
        float* svrow = &sv[ch * SVP];
#pragma unroll
        for (int m = 0; m < 35; ++m) {
            const int j = grp * 35 + m;   // 0..139
            float u;
            if (!(j & 1)) {               // tp odd
                const float* p = xrow + (j >> 1) + 8;
                u = u0*p[0] + u2*p[-1] + u4*p[-2] + u6*p[-3] + u8*p[-4] + u10*p[-5];
            } else {                      // tp even
                const float* p = xrow + ((j - 5) >> 1) + 8;
                u = u1*p[2] + u3*p[1] + u5*p[0] + u7*p[-1] + u9*p[-2] + u11*p[-3];
            }
            u *= 2.0f;
            const float s = __sinf(u * alpha);
            svrow[j] = u + s * s * invb;
        }
    }
    __syncthreads();

    // edge replication (reference clamps v index to [0, 2T-1])
    if (t0 == 0) {
        for (int i = tid; i < 64 * 5; i += 256) {
            const int ch = i / 5;
            sv[ch * SVP + (i % 5)] = sv[ch * SVP + 5];
        }
    }
    if (t0 == T_LEN - 64) {
        for (int i = tid; i < 64 * 5; i += 256) {
            const int ch = i / 5;
            sv[ch * SVP + 133 + (i % 5)] = sv[ch * SVP + 132];
        }
    }
    __syncthreads();

    // ---- phase 2: downsample 16 outputs/thread, stage into zt (= sx region) ----
    float* zt = sx;
    {
        const int cl = tid & 63;
        const int tg = tid >> 6;          // 0..3
        const float d0=sd[0],d1=sd[1],d2=sd[2],d3=sd[3],d4=sd[4],d5=sd[5],
                    d6=sd[6],d7=sd[7],d8=sd[8],d9=sd[9],d10=sd[10],d11=sd[11];
        const float* svrow = &sv[cl * SVP + tg * 32];
        float vw[12];
#pragma unroll
        for (int j = 0; j < 12; ++j) vw[j] = svrow[j];
#pragma unroll
        for (int o = 0; o < 16; ++o) {
            const float z = d0*vw[0] + d1*vw[1] + d2*vw[2] + d3*vw[3]
                          + d4*vw[4] + d5*vw[5] + d6*vw[6] + d7*vw[7]
                          + d8*vw[8] + d9*vw[9] + d10*vw[10] + d11*vw[11];
            const int tt  = tg * 16 + o;
            const int swz = (tt + (tt >> 2)) & 31;
            zt[tt * 64 + (cl ^ swz)] = z;
            if (o < 15) {
#pragma unroll
                for (int j = 0; j < 10; ++j) vw[j] = vw[j + 2];
                vw[10] = svrow[12 + 2 * o];
                vw[11] = svrow[13 + 2 * o];
            }
        }
    }
    __syncthreads();

    // write out: 64 rows x 128B ([b][t0+tt][C] at c0), coalesced uint4 segs
#pragma unroll
    for (int iter = 0; iter < 2; ++iter) {
        const int idx = tid + iter * 256;
        const int tt  = idx >> 3;
        const int seg = idx & 7;
        const int swz = (tt + (tt >> 2)) & 31;
        uint4 o4;
        uint32_t* ow = &o4.x;
#pragma unroll
        for (int k = 0; k < 4; ++k) {
            const int ca = seg * 8 + 2 * k;
            const float za = zt[tt * 64 + (ca ^ swz)];
            const float zb = zt[tt * 64 + ((ca + 1) ^ swz)];
            ow[k] = pack_f16x2(za, zb);
        }
        *reinterpret_cast<uint4*>(
            outT + ((size_t)(b * T_LEN + t0 + tt)) * CCH + c0 + seg * 8) = o4;
    }
}

// ---------------------------------------------------------------------------
// fp16 HMMA conv (128x128, 8 warps 4x2, 2-stage pipeline). Unchanged (best).
// ---------------------------------------------------------------------------
#define NST 16
#define BP  20
#define ASTAGE_W 6144
#define BSTAGE_W (130 * BP)
#define STAGE_W  (ASTAGE_W + BSTAGE_W)
#define CONV_SMEM (2 * STAGE_W * 4)

template <bool OUT_F16>
__global__ __launch_bounds__(256, 2)
void conv_tc(const __half* __restrict__ xt, const uint4* __restrict__ wperm,
             const float* __restrict__ bias, const float* __restrict__ resid,
             void* __restrict__ outv)
{
    extern __shared__ uint32_t Ssm[];

    const int tid  = threadIdx.x;
    const int wid  = tid >> 5;
    const int lane = tid & 31;
    const int wr   = wid >> 1;
    const int wc   = wid & 1;
    const int b    = blockIdx.z;
    const int cb   = blockIdx.y;
    const int co0  = cb * 128;
    const int t0   = blockIdx.x * 128;

    float acc[2][8][4];
#pragma unroll
    for (int i = 0; i < 2; i++)
#pragma unroll
        for (int j = 0; j < 8; j++)
#pragma unroll
            for (int r = 0; r < 4; r++) acc[i][j][r] = 0.0f;

    const uint32_t smem0 = smem_u32(Ssm);
    const char* browg = reinterpret_cast<const char*>(
        xt + ((size_t)(b * T_LEN + t0 - 1)) * CCH);

    const int lg = lane >> 3;
    const int lr = lane & 7;
    const uint32_t lbase = smem0 + ASTAGE_W * 4
        + (uint32_t)((wc * 64 + lr + ((lg & 2) ? 8 : 0)) * (BP * 4))
        + (uint32_t)((lg & 1) * 16);

    auto fill = [&](int st, int s) {
        const uint4* Asrc = wperm + ((size_t)(cb * 16 + st)) * 1536 + tid;
        const uint32_t dstA = smem0 + s * (STAGE_W * 4) + tid * 16;
#pragma unroll
        for (int it = 0; it < 6; ++it)
            cp_async16(dstA + it * 4096, Asrc + it * 256);
        const uint32_t dstB = smem0 + s * (STAGE_W * 4) + ASTAGE_W * 4;
        const char* bs = browg + st * 64;
#pragma unroll
        for (int it = 0; it < 3; ++it) {
            const int idx = tid + it * 256;
            if (idx < 520) {
                const int row = idx >> 2, seg = idx & 3;
                const int tg = t0 - 1 + row;
                const uint32_t sz = (tg >= 0 && tg < T_LEN) ? 16u : 0u;
                cp_async16s(dstB + row * (BP * 4) + seg * 16,
                            bs + (size_t)row * (CCH * 2) + seg * 16, sz);
            }
        }
        cp_commit();
    };

    fill(0, 0);

    for (int st = 0; st < NST; ++st) {
        const int s = st & 1;
        cp_wait<0>();
        __syncthreads();
        if (st + 1 < NST) fill(st + 1, s ^ 1);

        const uint32_t* As = Ssm + s * STAGE_W;
        const uint32_t lB = lbase + s * (STAGE_W * 4);
#pragma unroll
        for (int kk = 0; kk < 3; ++kk) {
#pragma unroll
            for (int ks = 0; ks < 2; ++ks) {
                uint4 afr[2];
#pragma unroll
                for (int mt = 0; mt < 2; ++mt)
                    afr[mt] = *reinterpret_cast<const uint4*>(
                        As + (((kk * 2 + ks) * 8 + wr * 2 + mt) * 32 + lane) * 4);
                uint2 bfr[8];
                const uint32_t bb = lB + kk * (BP * 4) + ks * 32;
#pragma unroll
                for (int ntp = 0; ntp < 4; ++ntp)
                    ldsm_x4(bfr[2*ntp].x, bfr[2*ntp].y,
                            bfr[2*ntp+1].x, bfr[2*ntp+1].y,
                            bb + ntp * (16 * BP * 4));
#pragma unroll
                for (int mt = 0; mt < 2; ++mt)
#pragma unroll
                    for (int nt = 0; nt < 8; ++nt)
                        mma_f16(acc[mt][nt],
                                reinterpret_cast<const uint32_t*>(&afr[mt]),
                                reinterpret_cast<const uint32_t*>(&bfr[nt]));
            }
        }
    }

    __syncthreads();

    const int gid = lane >> 2;
    const int tig = lane & 3;
#pragma unroll
    for (int mt = 0; mt < 2; ++mt) {
#pragma unroll
        for (int half = 0; half < 2; ++half) {
            const int co = co0 + wr * 32 + mt * 16 + gid + half * 8;
            const float bv = __ldg(bias + co);
            if (OUT_F16) {
                __half* orow = (__half*)outv + ((size_t)b * CCH + co) * T_LEN
                             + t0 + wc * 64;
#pragma unroll
                for (int nt = 0; nt < 8; ++nt) {
                    const int n = nt * 8 + tig * 2;
                    const float lo = acc[mt][nt][half * 2 + 0] + bv;
                    const float hi = acc[mt][nt][half * 2 + 1] + bv;
                    *reinterpret_cast<uint32_t*>(orow + n) = pack_f16x2(lo, hi);
                }
            } else {
                float* orow = (float*)outv + ((size_t)b * CCH + co) * T_LEN
                            + t0 + wc * 64;
                const float* rrow = resid + ((size_t)b * CCH + co) * T_LEN
                                  + t0 + wc * 64;
#pragma unroll
                for (int nt = 0; nt < 8; ++nt) {
                    const int n = nt * 8 + tig * 2;
                    float lo = acc[mt][nt][half * 2 + 0] + bv;
                    float hi = acc[mt][nt][half * 2 + 1] + bv;
                    float2 rv = *reinterpret_cast<const float2*>(rrow + n);
                    lo += rv.x; hi += rv.y;
                    float2 v; v.x = lo; v.y = hi;
                    *reinterpret_cast<float2*>(orow + n) = v;
                }
            }
        }
    }
}

// ---------------------------------------------------------------------------
extern "C" void kernel_launch(void* const* d_in, const int* in_sizes, int n_in,
                              void* d_out, int out_size)
{
    const float* x    = (const float*)d_in[0];
    const float* a1a  = (const float*)d_in[1];
    const float* a1b  = (const float*)d_in[2];
    const float* a2a  = (const float*)d_in[3];
    const float* a2b  = (const float*)d_in[4];
    const float* c1w  = (const float*)d_in[5];
    const float* c1b  = (const float*)d_in[6];
    const float* c2w  = (const float*)d_in[7];
    const float* c2b  = (const float*)d_in[8];
    const float* fup  = (const float*)d_in[9];
    const float* fdn  = (const float*)d_in[10];
    float* out = (float*)d_out;

    __half *gM, *gT;
    uint4 *wp1, *wp2;
    cudaGetSymbolAddress((void**)&gM, g_bufM);
    cudaGetSymbolAddress((void**)&gT, g_bufT);
    cudaGetSymbolAddress((void**)&wp1, g_wperm1);
    cudaGetSymbolAddress((void**)&wp2, g_wperm2);

    cudaFuncSetAttribute(conv_tc<true>,
                         cudaFuncAttributeMaxDynamicSharedMemorySize, CONV_SMEM);
    cudaFuncSetAttribute(conv_tc<false>,
                         cudaFuncAttributeMaxDynamicSharedMemorySize, CONV_SMEM);
    cudaFuncSetAttribute(actT_kernel<float>,
                         cudaFuncAttributeMaxDynamicSharedMemorySize, ACT_SMEM);
    cudaFuncSetAttribute(actT_kernel<__half>,
                         cudaFuncAttributeMaxDynamicSharedMemorySize, ACT_SMEM);

    dim3 gActT(T_LEN / 64, CCH / 64, BATCH);
    dim3 gConv(T_LEN / 128, CCH / 128, BATCH);

    permute_w<<<384, 256>>>(c1w, wp1);
    permute_w<<<384, 256>>>(c2w, wp2);

    actT_kernel<float><<<gActT, 256, ACT_SMEM>>>(x, gT, a1a, a1b, fup, fdn);
    conv_tc<true><<<gConv, 256, CONV_SMEM>>>(gT, wp1, c1b, nullptr, gM);
    actT_kernel<__half><<<gActT, 256, ACT_SMEM>>>(gM, gT, a2a, a2b, fup, fdn);
    conv_tc<false><<<gConv, 256, CONV_SMEM>>>(gT, wp2, c2b, x, out);
}